// round 2
// baseline (speedup 1.0000x reference)
#include <cuda_runtime.h>
#include <stdint.h>

#define N_OBJ 16384
#define N_DIM 4096

// 134 MB scratch: bin index per (dim, object), transposed layout [dim][object].
__device__ uint16_t g_bins[(size_t)N_DIM * N_OBJ];

// Threshold t_j = float32((j+1)/16384) * 0.05f, matching reference roundings exactly:
// (j+1)*2^-14 is exact in f32; single rounding on the *0.05f.
__device__ __forceinline__ float thr(int j) {
    return __fmul_rn(0.05f, (float)(j + 1) * 6.103515625e-05f);
}

__global__ void phase1_kernel(const float* __restrict__ q_mu,
                              const float* __restrict__ q_var) {
    __shared__ uint16_t tile[32][33];
    int d = blockIdx.x * 32 + threadIdx.x;   // dim (contiguous in input)
    int i = blockIdx.y * 32 + threadIdx.y;   // object
    size_t idx = (size_t)i * N_DIM + d;
    float m = q_mu[idx];
    float v = q_var[idx];
    float z = (-m / v) * 0.70710678118654752440f;
    float p = 0.5f * (1.0f + erff(z));

    uint16_t b = 0xFFFFu;
    if (p <= 0.05f) {   // == thr(N_OBJ-1) exactly
        int j = (int)(p * 327680.0f);        // rough estimate of min{j : p <= thr(j)}
        j = min(max(j, 0), N_OBJ - 1);
        while (j > 0 && p <= thr(j - 1)) --j;          // exact fixup (<=2 iters)
        while (j < N_OBJ - 1 && p > thr(j)) ++j;
        b = (uint16_t)j;
    }
    tile[threadIdx.y][threadIdx.x] = b;
    __syncthreads();
    // transposed coalesced write: bins[od][oi]
    int od = blockIdx.x * 32 + threadIdx.y;
    int oi = blockIdx.y * 32 + threadIdx.x;
    g_bins[(size_t)od * N_OBJ + oi] = tile[threadIdx.x][threadIdx.y];
}

__global__ void phase2_kernel(float* __restrict__ out) {
    extern __shared__ uint32_t hist[];       // N_OBJ * 4B = 64 KB (dynamic)
    __shared__ uint32_t warp_part[32];
    __shared__ uint32_t s_carry;
    __shared__ uint32_t red_cnt[32];
    __shared__ int      red_min[32];

    const int tid  = threadIdx.x;            // 1024 threads
    const int lane = tid & 31;
    const int wid  = tid >> 5;
    const int d    = blockIdx.x;

    for (int k = tid; k < N_OBJ; k += 1024) hist[k] = 0;
    if (tid == 0) s_carry = 0;
    __syncthreads();

    // Histogram of bin indices for this dim row.
    const uint16_t* row = g_bins + (size_t)d * N_OBJ;
    uint32_t zc = 0;                         // bin-0 is hot (p==0 saturation) -> aggregate
    #pragma unroll
    for (int it = 0; it < N_OBJ / 1024; ++it) {
        uint32_t b = row[it * 1024 + tid];
        if (b == 0u) zc++;
        else if (b != 0xFFFFu) atomicAdd(&hist[b], 1u);
    }
    #pragma unroll
    for (int o = 16; o > 0; o >>= 1) zc += __shfl_down_sync(0xffffffffu, zc, o);
    if (lane == 0 && zc) atomicAdd(&hist[0], zc);
    __syncthreads();

    // Chunked inclusive scan over 16384 bins:
    // reject[j] = (cumcount(j) >= j+1). Accumulate count and first index.
    uint32_t count = 0;
    int firstj = 0x7fffffff;
    for (int c = 0; c < N_OBJ / 1024; ++c) {
        int j = c * 1024 + tid;
        uint32_t x = hist[j];
        #pragma unroll
        for (int o = 1; o < 32; o <<= 1) {
            uint32_t y = __shfl_up_sync(0xffffffffu, x, o);
            if (lane >= o) x += y;
        }
        if (lane == 31) warp_part[wid] = x;
        __syncthreads();
        if (wid == 0) {
            uint32_t w = warp_part[lane];
            #pragma unroll
            for (int o = 1; o < 32; o <<= 1) {
                uint32_t y = __shfl_up_sync(0xffffffffu, w, o);
                if (lane >= o) w += y;
            }
            warp_part[lane] = w;
        }
        __syncthreads();
        uint32_t incl = x + (wid > 0 ? warp_part[wid - 1] : 0u) + s_carry;
        if (incl >= (uint32_t)(j + 1)) { count++; firstj = min(firstj, j); }
        __syncthreads();
        if (tid == 0) s_carry += warp_part[31];
        __syncthreads();
    }

    // Block reduce (sum count, min firstj).
    #pragma unroll
    for (int o = 16; o > 0; o >>= 1) {
        count += __shfl_down_sync(0xffffffffu, count, o);
        firstj = min(firstj, __shfl_down_sync(0xffffffffu, firstj, o));
    }
    if (lane == 0) { red_cnt[wid] = count; red_min[wid] = firstj; }
    __syncthreads();
    if (wid == 0) {
        uint32_t cc = red_cnt[lane];
        int mm = red_min[lane];
        #pragma unroll
        for (int o = 16; o > 0; o >>= 1) {
            cc += __shfl_down_sync(0xffffffffu, cc, o);
            mm = min(mm, __shfl_down_sync(0xffffffffu, mm, o));
        }
        if (lane == 0) {
            // importance = count_reject + first_idx (positions < first_idx flipped to True)
            uint32_t imp = cc + ((mm == 0x7fffffff) ? 0u : (uint32_t)mm);
            out[d] = (float)imp;
        }
    }
}

extern "C" void kernel_launch(void* const* d_in, const int* in_sizes, int n_in,
                              void* d_out, int out_size) {
    const float* q_mu  = (const float*)d_in[0];
    const float* q_var = (const float*)d_in[1];
    // d_in[2] (ecdf_factor) is reproduced exactly on device; not read.
    float* out = (float*)d_out;

    cudaFuncSetAttribute((const void*)phase2_kernel,
                         cudaFuncAttributeMaxDynamicSharedMemorySize,
                         N_OBJ * (int)sizeof(uint32_t));

    dim3 b1(32, 32);
    dim3 g1(N_DIM / 32, N_OBJ / 32);
    phase1_kernel<<<g1, b1>>>(q_mu, q_var);
    phase2_kernel<<<N_DIM, 1024, N_OBJ * sizeof(uint32_t)>>>(out);
}

// round 3
// speedup vs baseline: 1.5102x; 1.5102x over previous
#include <cuda_runtime.h>
#include <stdint.h>

#define N_OBJ 16384
#define N_DIM 4096
#define LUTN  8192
#define INV_SQRT2 0.70710678118654752440f

// 134 MB scratch: bin index per (dim, object), transposed layout [dim][object].
__device__ uint16_t g_bins[(size_t)N_DIM * N_OBJ];
__device__ float    g_zthr[N_OBJ];        // zthr[j] = max f32 z with p(z) <= thr(j)
__device__ uint16_t g_lut[LUTN + 1];      // bucket -> lower-bound j

// Threshold t_j = 0.05f * float32((j+1)/16384), matching reference roundings.
__device__ __forceinline__ float thr(int j) {
    return __fmul_rn(0.05f, (float)(j + 1) * 6.103515625e-05f);
}
__device__ __forceinline__ float pz(float z) {
    return 0.5f * (1.0f + erff(z));
}

// ---------------- init 1: z-space thresholds via bit-level binary search ---
__global__ void init_zthr_kernel() {
    int j = blockIdx.x * 256 + threadIdx.x;      // 16384 threads
    if (j >= N_OBJ) return;
    float t = thr(j);
    // z = -as_float(u), u positive-float bits; p(-as_float(u)) decreasing in u.
    // find min u with p <= t.
    unsigned lo = __float_as_uint(1e-10f);       // p ~ 0.5 > t
    unsigned hi = __float_as_uint(12.0f);        // erff(-12) == -1 -> p = 0 <= t
    while (lo < hi) {
        unsigned mid = (lo + hi) >> 1;
        if (pz(-__uint_as_float(mid)) <= t) hi = mid; else lo = mid + 1;
    }
    g_zthr[j] = -__uint_as_float(lo);
}

// ---------------- init 2: bucket LUT over [zthr[0], zthr[16383]] ----------
__global__ void init_lut_kernel() {
    int k = blockIdx.x * 256 + threadIdx.x;
    if (k > LUTN) return;
    float zlo = g_zthr[0], zhi = g_zthr[N_OBJ - 1];
    float zk = zlo + (zhi - zlo) * ((float)k / (float)LUTN);
    int lo = 0, hi = N_OBJ - 1;                   // min j with zthr[j] >= zk
    while (lo < hi) {
        int mid = (lo + hi) >> 1;
        if (g_zthr[mid] >= zk) hi = mid; else lo = mid + 1;
    }
    g_lut[k] = (uint16_t)lo;
}

// ---------------- phase 1: bins, persistent blocks, transposed write ------
// Tile = 32 dims x 256 objects. Block 1024 = (32 tx=dim, 32 ty=obj), 8 objs/thread.
#define DTILES (N_DIM / 32)     // 128
#define OTILES (N_OBJ / 256)    // 64
#define NTILES (DTILES * OTILES)
#define P1_ZOFF 0
#define P1_LOFF 65536
#define P1_TOFF (65536 + 16512)
#define P1_SMEM (P1_TOFF + 32 * 258 * 2)

__global__ __launch_bounds__(1024, 2) void phase1_kernel(
        const float* __restrict__ q_mu, const float* __restrict__ q_var) {
    extern __shared__ char sm[];
    float*    s_zthr = (float*)(sm + P1_ZOFF);
    uint16_t* s_lut  = (uint16_t*)(sm + P1_LOFF);
    uint16_t* s_tile = (uint16_t*)(sm + P1_TOFF);   // [32][258]

    const int tid = threadIdx.x, tx = tid & 31, ty = tid >> 5;
    for (int k = tid; k < N_OBJ; k += 1024) s_zthr[k] = g_zthr[k];
    for (int k = tid; k <= LUTN; k += 1024) s_lut[k] = g_lut[k];
    __syncthreads();

    const float zlo = s_zthr[0], zhi = s_zthr[N_OBJ - 1];
    const float invw = (float)LUTN / (zhi - zlo);
    uint32_t* bins32 = reinterpret_cast<uint32_t*>(g_bins);

    for (int t = blockIdx.x; t < NTILES; t += gridDim.x) {
        const int dt = t & (DTILES - 1);
        const int ot = t >> 7;                       // t / DTILES
        const int d = dt * 32 + tx;
        const size_t base = (size_t)(ot * 256 + ty) * N_DIM + d;

        float mm[8], vv[8];
        #pragma unroll
        for (int r = 0; r < 8; r++) {
            mm[r] = q_mu[base + (size_t)r * 32 * N_DIM];
            vv[r] = q_var[base + (size_t)r * 32 * N_DIM];
        }
        #pragma unroll
        for (int r = 0; r < 8; r++) {
            float z = (-mm[r] / vv[r]) * INV_SQRT2;
            uint16_t bin = 0xFFFFu;
            if (z <= zhi) {                          // p <= 0.05
                if (z <= zlo) bin = 0;
                else {
                    int k = (int)((z - zlo) * invw);
                    k = min(max(k, 0), LUTN - 1);
                    int lo = s_lut[k], hi = s_lut[k + 1];
                    while (lo < hi) {
                        int mid = (lo + hi) >> 1;
                        if (z <= s_zthr[mid]) hi = mid; else lo = mid + 1;
                    }
                    // safety fixup for any LUT/fp bucket edge mismatch
                    while (lo > 0 && z <= s_zthr[lo - 1]) --lo;
                    while (lo < N_OBJ - 1 && z > s_zthr[lo]) ++lo;
                    bin = (uint16_t)lo;
                }
            }
            s_tile[tx * 258 + (ty + r * 32)] = bin;
        }
        __syncthreads();
        // transposed coalesced store: 32 dims x 256 objs = 4096 u32
        #pragma unroll
        for (int q = 0; q < 4; q++) {
            int s = q * 1024 + tid;
            int dd = s >> 7, pp = s & 127;
            uint32_t val = *(const uint32_t*)&s_tile[dd * 258 + 2 * pp];
            bins32[((size_t)(dt * 32 + dd) * N_OBJ + ot * 256) / 2 + pp] = val;
        }
        __syncthreads();
    }
}

// ---------------- phase 2: per-dim histogram + bounded scan ---------------
__global__ __launch_bounds__(1024, 2) void phase2_kernel(float* __restrict__ out) {
    extern __shared__ uint32_t hist[];       // 16384 u32 = 64 KB
    __shared__ uint32_t warp_part[32];
    __shared__ uint32_t s_carry, s_C;
    __shared__ uint32_t red_cnt[32];
    __shared__ int      red_min[32];

    const int tid = threadIdx.x, lane = tid & 31, wid = tid >> 5;
    const int d = blockIdx.x;

    // row -> registers (16 u16 per thread)
    const uint4* row = (const uint4*)(g_bins + (size_t)d * N_OBJ);
    uint4 ra = row[tid];
    uint4 rb = row[tid + 1024];
    uint32_t w[8] = {ra.x, ra.y, ra.z, ra.w, rb.x, rb.y, rb.z, rb.w};

    // C = #(non-sentinel)
    uint32_t cnt = 0;
    #pragma unroll
    for (int q = 0; q < 8; q++) {
        cnt += ((w[q] & 0xFFFFu) != 0xFFFFu);
        cnt += ((w[q] >> 16)     != 0xFFFFu);
    }
    #pragma unroll
    for (int o = 16; o > 0; o >>= 1) cnt += __shfl_down_sync(0xffffffffu, cnt, o);
    if (tid == 0) { s_C = 0; s_carry = 0; }
    __syncthreads();
    if (lane == 0 && cnt) atomicAdd(&s_C, cnt);
    __syncthreads();

    const uint32_t C = s_C;
    const int chunks = min(16, (int)((C + 1023u) >> 10));
    const uint32_t limit = (uint32_t)chunks << 10;
    if (chunks == 0) { if (tid == 0) out[d] = 0.0f; return; }

    for (int k = tid; k < (int)limit; k += 1024) hist[k] = 0;
    __syncthreads();

    uint32_t zc = 0;                          // bin 0 is hot -> warp-aggregate
    #pragma unroll
    for (int q = 0; q < 8; q++) {
        uint32_t b0 = w[q] & 0xFFFFu, b1 = w[q] >> 16;
        if (b0 == 0u) zc++; else if (b0 < limit) atomicAdd(&hist[b0], 1u);
        if (b1 == 0u) zc++; else if (b1 < limit) atomicAdd(&hist[b1], 1u);
    }
    #pragma unroll
    for (int o = 16; o > 0; o >>= 1) zc += __shfl_down_sync(0xffffffffu, zc, o);
    if (lane == 0 && zc) atomicAdd(&hist[0], zc);
    __syncthreads();

    // chunked inclusive scan over [0, limit): reject[j] = cum(j) >= j+1
    uint32_t count = 0;
    int firstj = 0x7fffffff;
    for (int c = 0; c < chunks; ++c) {
        int j = c * 1024 + tid;
        uint32_t x = hist[j];
        #pragma unroll
        for (int o = 1; o < 32; o <<= 1) {
            uint32_t y = __shfl_up_sync(0xffffffffu, x, o);
            if (lane >= o) x += y;
        }
        if (lane == 31) warp_part[wid] = x;
        __syncthreads();
        if (wid == 0) {
            uint32_t ww = warp_part[lane];
            #pragma unroll
            for (int o = 1; o < 32; o <<= 1) {
                uint32_t y = __shfl_up_sync(0xffffffffu, ww, o);
                if (lane >= o) ww += y;
            }
            warp_part[lane] = ww;
        }
        __syncthreads();
        uint32_t incl = x + (wid > 0 ? warp_part[wid - 1] : 0u) + s_carry;
        if (incl >= (uint32_t)(j + 1)) { count++; firstj = min(firstj, j); }
        __syncthreads();
        if (tid == 0) s_carry += warp_part[31];
        __syncthreads();
    }

    #pragma unroll
    for (int o = 16; o > 0; o >>= 1) {
        count += __shfl_down_sync(0xffffffffu, count, o);
        firstj = min(firstj, __shfl_down_sync(0xffffffffu, firstj, o));
    }
    if (lane == 0) { red_cnt[wid] = count; red_min[wid] = firstj; }
    __syncthreads();
    if (wid == 0) {
        uint32_t cc = red_cnt[lane];
        int mm = red_min[lane];
        #pragma unroll
        for (int o = 16; o > 0; o >>= 1) {
            cc += __shfl_down_sync(0xffffffffu, cc, o);
            mm = min(mm, __shfl_down_sync(0xffffffffu, mm, o));
        }
        if (lane == 0) {
            uint32_t imp = cc + ((mm == 0x7fffffff) ? 0u : (uint32_t)mm);
            out[d] = (float)imp;
        }
    }
}

extern "C" void kernel_launch(void* const* d_in, const int* in_sizes, int n_in,
                              void* d_out, int out_size) {
    const float* q_mu  = (const float*)d_in[0];
    const float* q_var = (const float*)d_in[1];
    float* out = (float*)d_out;

    cudaFuncSetAttribute((const void*)phase1_kernel,
                         cudaFuncAttributeMaxDynamicSharedMemorySize, P1_SMEM);
    cudaFuncSetAttribute((const void*)phase2_kernel,
                         cudaFuncAttributeMaxDynamicSharedMemorySize,
                         N_OBJ * (int)sizeof(uint32_t));

    init_zthr_kernel<<<N_OBJ / 256, 256>>>();
    init_lut_kernel<<<(LUTN + 256) / 256 + 1, 256>>>();
    phase1_kernel<<<296, 1024, P1_SMEM>>>(q_mu, q_var);
    phase2_kernel<<<N_DIM, 1024, N_OBJ * sizeof(uint32_t)>>>(out);
}